// round 1
// baseline (speedup 1.0000x reference)
#include <cuda_runtime.h>
#include <math_constants.h>

// Chamfer distance: B=8, N=M=4096, D=2.
// Per (batch, dir): queries scan a 4096-point DB staged in smem as
// (u0,u1,h) = (-2*t0, -2*t1, |t|^2);  score s = h + qx*u0 + qy*u1;
// d = sqrt(max(0, |q|^2 + min_s)).  Sum all 65536 d's * (1/32768).

#define NPTS    4096
#define THREADS 256
#define TILES   16          // queries per tile = NPTS/TILES = 256 = THREADS

__global__ __launch_bounds__(THREADS)
void chamfer_kernel(const float* __restrict__ x,
                    const float* __restrict__ tgt,
                    float* __restrict__ out)
{
    extern __shared__ float4 s_db[];          // 4096 * 16B = 64 KB
    __shared__ float s_warp[THREADS / 32];

    const int tile = blockIdx.x & (TILES - 1);
    const int pair = blockIdx.x >> 4;         // 0..15
    const int dir  = pair & 1;
    const int b    = pair >> 1;

    const float* q_base = (dir ? tgt : x) + (size_t)b * NPTS * 2;
    const float* d_base = (dir ? x : tgt) + (size_t)b * NPTS * 2;

    // Stage DB into smem with the precompute baked in.
    const float2* dbp = (const float2*)d_base;
    #pragma unroll
    for (int i = threadIdx.x; i < NPTS; i += THREADS) {
        float2 t = dbp[i];
        s_db[i] = make_float4(-2.0f * t.x, -2.0f * t.y,
                              fmaf(t.x, t.x, t.y * t.y), 0.0f);
    }
    __syncthreads();

    const int qi = tile * THREADS + threadIdx.x;   // always < NPTS
    const float2 q = ((const float2*)q_base)[qi];
    const float q2 = fmaf(q.x, q.x, q.y * q.y);

    // 4 independent accumulators break the FMNMX RAW chain.
    float m0 = CUDART_INF_F, m1 = CUDART_INF_F;
    float m2 = CUDART_INF_F, m3 = CUDART_INF_F;

    #pragma unroll 2
    for (int j = 0; j < NPTS; j += 4) {
        float4 t0 = s_db[j + 0];
        float4 t1 = s_db[j + 1];
        float4 t2 = s_db[j + 2];
        float4 t3 = s_db[j + 3];
        float s0 = fmaf(q.x, t0.x, fmaf(q.y, t0.y, t0.z));
        float s1 = fmaf(q.x, t1.x, fmaf(q.y, t1.y, t1.z));
        float s2 = fmaf(q.x, t2.x, fmaf(q.y, t2.y, t2.z));
        float s3 = fmaf(q.x, t3.x, fmaf(q.y, t3.y, t3.z));
        m0 = fminf(m0, s0);
        m1 = fminf(m1, s1);
        m2 = fminf(m2, s2);
        m3 = fminf(m3, s3);
    }
    float m = fminf(fminf(m0, m1), fminf(m2, m3));
    float d = sqrtf(fmaxf(q2 + m, 0.0f));

    // Block reduction of d.
    float v = d;
    #pragma unroll
    for (int off = 16; off > 0; off >>= 1)
        v += __shfl_down_sync(0xFFFFFFFFu, v, off);
    const int lane = threadIdx.x & 31;
    const int wid  = threadIdx.x >> 5;
    if (lane == 0) s_warp[wid] = v;
    __syncthreads();
    if (wid == 0) {
        float w = (lane < THREADS / 32) ? s_warp[lane] : 0.0f;
        #pragma unroll
        for (int off = 4; off > 0; off >>= 1)
            w += __shfl_down_sync(0xFFFFFFFFu, w, off);
        if (lane == 0)
            atomicAdd(out, w * (1.0f / 32768.0f));
    }
}

extern "C" void kernel_launch(void* const* d_in, const int* in_sizes, int n_in,
                              void* d_out, int out_size)
{
    const float* x   = (const float*)d_in[0];   // [8,4096,2] f32
    const float* tgt = (const float*)d_in[1];   // [8,4096,2] f32
    float* out = (float*)d_out;                 // scalar f32

    (void)in_sizes; (void)n_in; (void)out_size;

    static const size_t SMEM = NPTS * sizeof(float4);   // 64 KB
    cudaFuncSetAttribute(chamfer_kernel,
                         cudaFuncAttributeMaxDynamicSharedMemorySize, (int)SMEM);

    cudaMemsetAsync(d_out, 0, sizeof(float));
    chamfer_kernel<<<16 * TILES, THREADS, SMEM>>>(x, tgt, out);
}

// round 2
// speedup vs baseline: 1.9500x; 1.9500x over previous
#include <cuda_runtime.h>
#include <math_constants.h>

// Chamfer distance: B=8, N=M=4096, D=2 on sm_100a.
// Pass 1: for each (b,dir,dbsplit), queries scan a 2048-point DB chunk staged
//   in smem in packed-pair form:
//     s_uv[p]  = (u0_{2p}, u0_{2p+1}, u1_{2p}, u1_{2p+1})  with u = -2*t
//     s_h2[p]  = (h_{2p}, h_{2p+1})                        with h = |t|^2
//   Score s = h + qx*u0 + qy*u1 computed 2-points-at-a-time with fma.rn.f32x2.
//   Each thread handles Q=2 queries -> LDS amortized 4x per query-pair.
//   Writes per-query partial min to scratch.
// Pass 2: combine 2 partials, add |q|^2, sqrt, reduce-sum, atomicAdd.

#define NPTS    4096
#define THREADS 256
#define Q       2
#define DBSPLIT 2
#define DBCHUNK (NPTS / DBSPLIT)            // 2048 points
#define QTILES  (NPTS / (THREADS * Q))      // 8
#define NPAIRS  16                          // 8 batches x 2 directions

__device__ float g_pmin[DBSPLIT * NPAIRS * NPTS];   // 512 KB scratch

__device__ __forceinline__ unsigned long long ffma2(unsigned long long a,
                                                    unsigned long long b,
                                                    unsigned long long c)
{
    unsigned long long d;
    asm("fma.rn.f32x2 %0, %1, %2, %3;" : "=l"(d) : "l"(a), "l"(b), "l"(c));
    return d;
}

__device__ __forceinline__ unsigned long long pack2(float lo, float hi)
{
    unsigned long long r;
    asm("mov.b64 %0, {%1, %2};" : "=l"(r) : "f"(lo), "f"(hi));
    return r;
}

__device__ __forceinline__ void unpack2(unsigned long long v, float& lo, float& hi)
{
    asm("mov.b64 {%0, %1}, %2;" : "=f"(lo), "=f"(hi) : "l"(v));
}

__global__ __launch_bounds__(THREADS)
void chamfer_pass1(const float* __restrict__ x, const float* __restrict__ tgt)
{
    __shared__ __align__(16) float4 s_uv[DBCHUNK / 2];   // 16 KB
    __shared__ __align__(16) float2 s_h2[DBCHUNK / 2];   //  8 KB

    const int blk   = blockIdx.x;
    const int qtile = blk & (QTILES - 1);
    const int pair  = (blk >> 3) & (NPAIRS - 1);
    const int split = blk >> 7;
    const int dir   = pair & 1;
    const int b     = pair >> 1;

    const float* q_base = (dir ? tgt : x) + (size_t)b * NPTS * 2;
    const float* d_base = (dir ? x : tgt) + (size_t)b * NPTS * 2
                          + (size_t)split * DBCHUNK * 2;

    // Stage DB chunk: each iteration handles one point-pair (float4 = 2 points).
    const float4* db4 = (const float4*)d_base;
    #pragma unroll
    for (int p = threadIdx.x; p < DBCHUNK / 2; p += THREADS) {
        float4 t = db4[p];                  // (t0x, t0y, t1x, t1y)
        s_uv[p] = make_float4(-2.0f * t.x, -2.0f * t.z,
                              -2.0f * t.y, -2.0f * t.w);
        s_h2[p] = make_float2(fmaf(t.x, t.x, t.y * t.y),
                              fmaf(t.z, t.z, t.w * t.w));
    }
    __syncthreads();

    const int qi0 = qtile * (THREADS * Q) + threadIdx.x;
    const int qi1 = qi0 + THREADS;
    const float2 qa = ((const float2*)q_base)[qi0];
    const float2 qc = ((const float2*)q_base)[qi1];

    const unsigned long long qxx0 = pack2(qa.x, qa.x);
    const unsigned long long qyy0 = pack2(qa.y, qa.y);
    const unsigned long long qxx1 = pack2(qc.x, qc.x);
    const unsigned long long qyy1 = pack2(qc.y, qc.y);

    float m0 = CUDART_INF_F, m1 = CUDART_INF_F, m2 = CUDART_INF_F, m3 = CUDART_INF_F;
    float m4 = CUDART_INF_F, m5 = CUDART_INF_F, m6 = CUDART_INF_F, m7 = CUDART_INF_F;

    const ulonglong2* uvp = (const ulonglong2*)s_uv;   // [pair]: (u0pk, u1pk)
    const ulonglong2* hpp = (const ulonglong2*)s_h2;   // [i]: h of points 4i..4i+3

    #pragma unroll 4
    for (int i = 0; i < DBCHUNK / 4; i++) {            // 4 points per iter
        ulonglong2 uvA = uvp[2 * i];
        ulonglong2 uvB = uvp[2 * i + 1];
        ulonglong2 hh  = hpp[i];

        unsigned long long sA0 = ffma2(qxx0, uvA.x, ffma2(qyy0, uvA.y, hh.x));
        unsigned long long sB0 = ffma2(qxx0, uvB.x, ffma2(qyy0, uvB.y, hh.y));
        unsigned long long sA1 = ffma2(qxx1, uvA.x, ffma2(qyy1, uvA.y, hh.x));
        unsigned long long sB1 = ffma2(qxx1, uvB.x, ffma2(qyy1, uvB.y, hh.y));

        float a, c;
        unpack2(sA0, a, c);  m0 = fminf(m0, a);  m1 = fminf(m1, c);
        unpack2(sB0, a, c);  m2 = fminf(m2, a);  m3 = fminf(m3, c);
        unpack2(sA1, a, c);  m4 = fminf(m4, a);  m5 = fminf(m5, c);
        unpack2(sB1, a, c);  m6 = fminf(m6, a);  m7 = fminf(m7, c);
    }

    float mq0 = fminf(fminf(m0, m1), fminf(m2, m3));
    float mq1 = fminf(fminf(m4, m5), fminf(m6, m7));

    float* dst = g_pmin + ((size_t)split * NPAIRS + pair) * NPTS;
    dst[qi0] = mq0;
    dst[qi1] = mq1;
}

__global__ __launch_bounds__(THREADS)
void chamfer_pass2(const float* __restrict__ x, const float* __restrict__ tgt,
                   float* __restrict__ out)
{
    __shared__ float s_warp[THREADS / 32];

    const int pair = blockIdx.x >> 4;          // 0..15
    const int tile = blockIdx.x & 15;          // 0..15
    const int dir  = pair & 1;
    const int b    = pair >> 1;
    const int qi   = tile * THREADS + threadIdx.x;

    const float* q_base = (dir ? tgt : x) + (size_t)b * NPTS * 2;
    const float2 q = ((const float2*)q_base)[qi];
    const float q2 = fmaf(q.x, q.x, q.y * q.y);

    float m = fminf(g_pmin[((size_t)0 * NPAIRS + pair) * NPTS + qi],
                    g_pmin[((size_t)1 * NPAIRS + pair) * NPTS + qi]);
    float v = sqrtf(fmaxf(q2 + m, 0.0f));

    #pragma unroll
    for (int off = 16; off > 0; off >>= 1)
        v += __shfl_down_sync(0xFFFFFFFFu, v, off);
    const int lane = threadIdx.x & 31;
    const int wid  = threadIdx.x >> 5;
    if (lane == 0) s_warp[wid] = v;
    __syncthreads();
    if (wid == 0) {
        float w = (lane < THREADS / 32) ? s_warp[lane] : 0.0f;
        #pragma unroll
        for (int off = 4; off > 0; off >>= 1)
            w += __shfl_down_sync(0xFFFFFFFFu, w, off);
        if (lane == 0)
            atomicAdd(out, w * (1.0f / 32768.0f));
    }
}

extern "C" void kernel_launch(void* const* d_in, const int* in_sizes, int n_in,
                              void* d_out, int out_size)
{
    const float* x   = (const float*)d_in[0];   // [8,4096,2] f32
    const float* tgt = (const float*)d_in[1];   // [8,4096,2] f32
    float* out = (float*)d_out;

    (void)in_sizes; (void)n_in; (void)out_size;

    cudaMemsetAsync(d_out, 0, sizeof(float));
    chamfer_pass1<<<DBSPLIT * NPAIRS * QTILES, THREADS>>>(x, tgt);
    chamfer_pass2<<<NPAIRS * 16, THREADS>>>(x, tgt, out);
}